// round 6
// baseline (speedup 1.0000x reference)
#include <cuda_runtime.h>

#define Bsz 32
#define Hh 480
#define Ww 640
#define HW (Hh*Ww)          // 307200 pixels per plane
#define HW4 (HW/4)          // 76800 float4 per plane
#define NPAIR (Bsz/2)       // 16 image pairs
#define NBLK 600            // 300 blocks per image of a pair
#define TPB 256             // 300*256 = 76800 = HW4 -> 1 triple per thread per image

__device__ float d_gray_sum[Bsz];
__device__ int   d_cnt[NPAIR];

__global__ void init_state() {
    int t = threadIdx.x;
    if (t < Bsz)   d_gray_sum[t] = 0.0f;
    if (t < NPAIR) d_cnt[t] = 0;
}

__device__ __forceinline__ float clip01(float v) {
    return fminf(fmaxf(v, 0.0f), 1.0f);
}

__global__ void __launch_bounds__(TPB, 5)
fused_color(const float* __restrict__ x,
            const float* __restrict__ bfv,
            const float* __restrict__ cfv,
            const float* __restrict__ sfv,
            const float* __restrict__ hfv,
            float* __restrict__ out) {
    const int blk  = blockIdx.x;
    const int half = (blk >= NBLK / 2) ? 1 : 0;           // 0: even image, 1: odd image
    const int slot = blk - half * (NBLK / 2);             // 0..299
    const int t4   = slot * TPB + threadIdx.x;            // triple index 0..HW4-1

    __shared__ float warp_part[TPB / 32];
    const int lane = threadIdx.x & 31;
    const int wid  = threadIdx.x >> 5;

    // ---- phase 1 helper: reduce this block's slice of pair p ----
    auto reduce_pair = [&](int p) {
        const int img = 2 * p + half;
        const float s = bfv[img];
        const float4* base = (const float4*)(x) + (size_t)img * 3 * HW4;
        float4 r4 = base[t4];
        float4 g4 = base[t4 + HW4];
        float4 b4 = base[t4 + 2 * HW4];

        float acc;
        {
            float r = clip01(r4.x * s), g = clip01(g4.x * s), b = clip01(b4.x * s);
            acc  = 0.299f * r + 0.587f * g + 0.114f * b;
            r = clip01(r4.y * s); g = clip01(g4.y * s); b = clip01(b4.y * s);
            acc += 0.299f * r + 0.587f * g + 0.114f * b;
            r = clip01(r4.z * s); g = clip01(g4.z * s); b = clip01(b4.z * s);
            acc += 0.299f * r + 0.587f * g + 0.114f * b;
            r = clip01(r4.w * s); g = clip01(g4.w * s); b = clip01(b4.w * s);
            acc += 0.299f * r + 0.587f * g + 0.114f * b;
        }
        for (int off = 16; off > 0; off >>= 1)
            acc += __shfl_down_sync(0xFFFFFFFF, acc, off);
        if (lane == 0) warp_part[wid] = acc;
        __syncthreads();
        if (wid == 0) {
            float v = (lane < TPB / 32) ? warp_part[lane] : 0.0f;
            for (int off = 4; off > 0; off >>= 1)
                v += __shfl_down_sync(0xFFFFFFFF, v, off);
            if (lane == 0) {
                atomicAdd(&d_gray_sum[img], v);
                __threadfence();
                atomicAdd(&d_cnt[p], 1);
            }
        }
        __syncthreads();   // protect warp_part for next use
    };

    // ---- software pipeline: reduce runs 2 pairs ahead of transform ----
    reduce_pair(0);
    reduce_pair(1);

    for (int p = 0; p < NPAIR; p++) {
        if (p + 2 < NPAIR) reduce_pair(p + 2);

        if (threadIdx.x == 0) {
            while (((volatile int*)d_cnt)[p] < NBLK) __nanosleep(64);
        }
        __syncthreads();

        // ---- transform this block's slice of pair p (input hits L2) ----
        const int img = 2 * p + half;
        const float bf = bfv[img];
        const float cf = cfv[img];
        const float sf = sfv[img];
        const float hf = hfv[img];
        const float mean = __ldcg(&d_gray_sum[img]) * (1.0f / (float)HW);

        const float4* ibase = (const float4*)(x)   + (size_t)img * 3 * HW4;
        float4*       obase = (float4*)(out)       + (size_t)img * 3 * HW4;

        float4 rv = __ldcs(ibase + t4);
        float4 gv = __ldcs(ibase + t4 + HW4);
        float4 bv = __ldcs(ibase + t4 + 2 * HW4);

        float rr[4] = {rv.x, rv.y, rv.z, rv.w};
        float gg[4] = {gv.x, gv.y, gv.z, gv.w};
        float bb[4] = {bv.x, bv.y, bv.z, bv.w};

        #pragma unroll
        for (int k = 0; k < 4; k++) {
            float r  = clip01(rr[k] * bf);
            float g  = clip01(gg[k] * bf);
            float bl = clip01(bb[k] * bf);
            r  = clip01(cf * r  + (1.0f - cf) * mean);
            g  = clip01(cf * g  + (1.0f - cf) * mean);
            bl = clip01(cf * bl + (1.0f - cf) * mean);
            float gray = 0.299f * r + 0.587f * g + 0.114f * bl;
            r  = clip01(sf * r  + (1.0f - sf) * gray);
            g  = clip01(sf * g  + (1.0f - sf) * gray);
            bl = clip01(sf * bl + (1.0f - sf) * gray);

            float maxc = fmaxf(r, fmaxf(g, bl));
            float minc = fminf(r, fminf(g, bl));
            float v  = maxc;
            float cr = maxc - minc;
            float crd = (cr == 0.0f) ? 1.0f : cr;
            float s = cr / ((maxc == 0.0f) ? 1.0f : maxc);
            float inv_crd = 1.0f / crd;
            float rc = (maxc - r)  * inv_crd;
            float gc = (maxc - g)  * inv_crd;
            float bc = (maxc - bl) * inv_crd;
            float hh;
            if (maxc == r)      hh = bc - gc;
            else if (maxc == g) hh = 2.0f + rc - bc;
            else                hh = 4.0f + gc - rc;
            float h = hh * (1.0f / 6.0f);
            h = h - floorf(h);
            h = h + hf;
            h = h - floorf(h);
            float i6 = h * 6.0f;
            float fi = floorf(i6);
            float f  = i6 - fi;
            int i = ((int)fi) % 6;
            float pp = v * (1.0f - s);
            float q  = v * (1.0f - f * s);
            float t  = v * (1.0f - (1.0f - f) * s);
            float r2, g2, b2;
            switch (i) {
                case 0:  r2 = v;  g2 = t;  b2 = pp; break;
                case 1:  r2 = q;  g2 = v;  b2 = pp; break;
                case 2:  r2 = pp; g2 = v;  b2 = t;  break;
                case 3:  r2 = pp; g2 = q;  b2 = v;  break;
                case 4:  r2 = t;  g2 = pp; b2 = v;  break;
                default: r2 = v;  g2 = pp; b2 = q;  break;
            }
            rr[k] = r2; gg[k] = g2; bb[k] = b2;
        }

        __stcs(obase + t4,           make_float4(rr[0], rr[1], rr[2], rr[3]));
        __stcs(obase + t4 + HW4,     make_float4(gg[0], gg[1], gg[2], gg[3]));
        __stcs(obase + t4 + 2 * HW4, make_float4(bb[0], bb[1], bb[2], bb[3]));
    }
}

extern "C" void kernel_launch(void* const* d_in, const int* in_sizes, int n_in,
                              void* d_out, int out_size) {
    const float* x  = (const float*)d_in[0];
    const float* bf = (const float*)d_in[1];
    const float* cf = (const float*)d_in[2];
    const float* sf = (const float*)d_in[3];
    const float* hf = (const float*)d_in[4];
    float* out = (float*)d_out;

    init_state<<<1, 64>>>();
    fused_color<<<NBLK, TPB>>>(x, bf, cf, sf, hf, out);
}

// round 10
// speedup vs baseline: 1.4011x; 1.4011x over previous
#include <cuda_runtime.h>

#define Bsz 32
#define Hh 480
#define Ww 640
#define HW (Hh*Ww)          // 307200 pixels per channel-plane
#define HW4 (HW/4)          // 76800 float4 per plane
#define TPB 256
#define PBLK (HW4/TPB)      // 300 blocks per image (both passes)

__device__ float d_part[Bsz * PBLK];   // per-block partial gray sums (overwritten each call)

__device__ __forceinline__ float clip01(float v) {
    return fminf(fmaxf(v, 0.0f), 1.0f);
}

// Pass 1: per-block partial sum of gray(clip(x * bf)).  grid = (PBLK, B), block = 256.
// Default load policy: leave input resident in L2 for pass 2.
// x-major block order -> images stream through L2 in order 0..31 (tail freshest).
__global__ void __launch_bounds__(TPB) gray_reduce(const float* __restrict__ x,
                                                   const float* __restrict__ bf) {
    const int b    = blockIdx.y;
    const int slot = blockIdx.x;
    const int g4   = slot * TPB + threadIdx.x;
    const float s  = bf[b];

    const float4* base = (const float4*)(x) + (size_t)b * 3 * HW4;
    float4 r4 = base[g4];
    float4 g4v = base[g4 + HW4];
    float4 b4 = base[g4 + 2 * HW4];

    float acc;
    {
        float r = clip01(r4.x * s), g = clip01(g4v.x * s), bb = clip01(b4.x * s);
        acc  = 0.299f * r + 0.587f * g + 0.114f * bb;
        r = clip01(r4.y * s); g = clip01(g4v.y * s); bb = clip01(b4.y * s);
        acc += 0.299f * r + 0.587f * g + 0.114f * bb;
        r = clip01(r4.z * s); g = clip01(g4v.z * s); bb = clip01(b4.z * s);
        acc += 0.299f * r + 0.587f * g + 0.114f * bb;
        r = clip01(r4.w * s); g = clip01(g4v.w * s); bb = clip01(b4.w * s);
        acc += 0.299f * r + 0.587f * g + 0.114f * bb;
    }

    for (int off = 16; off > 0; off >>= 1)
        acc += __shfl_down_sync(0xFFFFFFFF, acc, off);

    __shared__ float warp_part[TPB / 32];
    const int lane = threadIdx.x & 31;
    const int wid  = threadIdx.x >> 5;
    if (lane == 0) warp_part[wid] = acc;
    __syncthreads();
    if (wid == 0) {
        float v = (lane < TPB / 32) ? warp_part[lane] : 0.0f;
        for (int off = 4; off > 0; off >>= 1)
            v += __shfl_down_sync(0xFFFFFFFF, v, off);
        if (lane == 0) d_part[b * PBLK + slot] = v;
    }
}

// Pass 2: fused transform.  Images processed in REVERSE order (31..0) so the
// first waves read the L2-freshest data from pass 1 (LIFO reuse).
// Each block first re-reduces its image's 300 partials (deterministic mean).
__global__ void __launch_bounds__(TPB) color_xform(const float* __restrict__ x,
                            const float* __restrict__ bfv,
                            const float* __restrict__ cfv,
                            const float* __restrict__ sfv,
                            const float* __restrict__ hfv,
                            float* __restrict__ out) {
    const int blk  = blockIdx.x;                 // 0 .. B*PBLK-1
    const int b    = (Bsz - 1) - blk / PBLK;     // reversed image order
    const int slot = blk % PBLK;
    const int g4   = slot * TPB + threadIdx.x;

    const float4* ibase = (const float4*)(x) + (size_t)b * 3 * HW4;
    float4*       obase = (float4*)(out)     + (size_t)b * 3 * HW4;

    // Issue the long-latency pixel loads first (overlap with partial reduction).
    float4 rv = __ldcs(ibase + g4);
    float4 gv = __ldcs(ibase + g4 + HW4);
    float4 bv = __ldcs(ibase + g4 + 2 * HW4);

    // Re-reduce the 300 per-block partials for this image (L2-hot, 1.2 KB).
    const int t = threadIdx.x;
    float acc = d_part[b * PBLK + t];
    if (t < PBLK - TPB) acc += d_part[b * PBLK + t + TPB];
    for (int off = 16; off > 0; off >>= 1)
        acc += __shfl_down_sync(0xFFFFFFFF, acc, off);
    __shared__ float warp_part[TPB / 32];
    __shared__ float s_mean;
    const int lane = t & 31;
    const int wid  = t >> 5;
    if (lane == 0) warp_part[wid] = acc;
    __syncthreads();
    if (wid == 0) {
        float v = (lane < TPB / 32) ? warp_part[lane] : 0.0f;
        for (int off = 4; off > 0; off >>= 1)
            v += __shfl_down_sync(0xFFFFFFFF, v, off);
        if (lane == 0) s_mean = v * (1.0f / (float)HW);
    }
    __syncthreads();
    const float mean = s_mean;

    const float bf = bfv[b];
    const float cf = cfv[b];
    const float sf = sfv[b];
    const float hf = hfv[b];

    float rr[4] = {rv.x, rv.y, rv.z, rv.w};
    float gg[4] = {gv.x, gv.y, gv.z, gv.w};
    float bb[4] = {bv.x, bv.y, bv.z, bv.w};

    #pragma unroll
    for (int k = 0; k < 4; k++) {
        float r  = clip01(rr[k] * bf);
        float g  = clip01(gg[k] * bf);
        float bl = clip01(bb[k] * bf);
        r  = clip01(cf * r  + (1.0f - cf) * mean);
        g  = clip01(cf * g  + (1.0f - cf) * mean);
        bl = clip01(cf * bl + (1.0f - cf) * mean);
        float gray = 0.299f * r + 0.587f * g + 0.114f * bl;
        r  = clip01(sf * r  + (1.0f - sf) * gray);
        g  = clip01(sf * g  + (1.0f - sf) * gray);
        bl = clip01(sf * bl + (1.0f - sf) * gray);

        float maxc = fmaxf(r, fmaxf(g, bl));
        float minc = fminf(r, fminf(g, bl));
        float v  = maxc;
        float cr = maxc - minc;
        float crd = (cr == 0.0f) ? 1.0f : cr;
        float s = cr / ((maxc == 0.0f) ? 1.0f : maxc);
        float inv_crd = 1.0f / crd;
        float rc = (maxc - r)  * inv_crd;
        float gc = (maxc - g)  * inv_crd;
        float bc = (maxc - bl) * inv_crd;
        float hh;
        if (maxc == r)      hh = bc - gc;
        else if (maxc == g) hh = 2.0f + rc - bc;
        else                hh = 4.0f + gc - rc;
        float h = hh * (1.0f / 6.0f);
        h = h - floorf(h);
        h = h + hf;
        h = h - floorf(h);
        float i6 = h * 6.0f;
        float fi = floorf(i6);
        float f  = i6 - fi;
        int i = ((int)fi) % 6;
        float p = v * (1.0f - s);
        float q = v * (1.0f - f * s);
        float tt = v * (1.0f - (1.0f - f) * s);
        float r2, g2, b2;
        switch (i) {
            case 0:  r2 = v;  g2 = tt; b2 = p;  break;
            case 1:  r2 = q;  g2 = v;  b2 = p;  break;
            case 2:  r2 = p;  g2 = v;  b2 = tt; break;
            case 3:  r2 = p;  g2 = q;  b2 = v;  break;
            case 4:  r2 = tt; g2 = p;  b2 = v;  break;
            default: r2 = v;  g2 = p;  b2 = q;  break;
        }
        rr[k] = r2; gg[k] = g2; bb[k] = b2;
    }

    __stcs(obase + g4,           make_float4(rr[0], rr[1], rr[2], rr[3]));
    __stcs(obase + g4 + HW4,     make_float4(gg[0], gg[1], gg[2], gg[3]));
    __stcs(obase + g4 + 2 * HW4, make_float4(bb[0], bb[1], bb[2], bb[3]));
}

extern "C" void kernel_launch(void* const* d_in, const int* in_sizes, int n_in,
                              void* d_out, int out_size) {
    const float* x  = (const float*)d_in[0];
    const float* bf = (const float*)d_in[1];
    const float* cf = (const float*)d_in[2];
    const float* sf = (const float*)d_in[3];
    const float* hf = (const float*)d_in[4];
    float* out = (float*)d_out;

    gray_reduce<<<dim3(PBLK, Bsz), TPB>>>(x, bf);
    color_xform<<<Bsz * PBLK, TPB>>>(x, bf, cf, sf, hf, out);
}

// round 11
// speedup vs baseline: 1.6780x; 1.1977x over previous
#include <cuda_runtime.h>

#define Bsz 32
#define Hh 480
#define Ww 640
#define HW (Hh*Ww)          // 307200 pixels per channel-plane
#define HW4 (HW/4)          // 76800 float4 per plane
#define TPB 256
#define PBLK (HW4/TPB)      // 300 blocks per image (both passes)

__device__ float d_part[Bsz * PBLK];   // per-block partial gray sums (overwritten each call)

__device__ __forceinline__ float clip01(float v) {
    return fminf(fmaxf(v, 0.0f), 1.0f);
}

// Pass 1: per-block partial sum of gray(clip(x * bf)).  grid = (PBLK, B), block = 256.
// Default load policy: leave input resident in L2 for pass 2 (LIFO reuse).
__global__ void __launch_bounds__(TPB) gray_reduce(const float* __restrict__ x,
                                                   const float* __restrict__ bf) {
    const int b    = blockIdx.y;
    const int slot = blockIdx.x;
    const int g4   = slot * TPB + threadIdx.x;
    const float s  = bf[b];

    const float4* base = (const float4*)(x) + (size_t)b * 3 * HW4;
    float4 r4 = base[g4];
    float4 g4v = base[g4 + HW4];
    float4 b4 = base[g4 + 2 * HW4];

    float acc;
    {
        float r = clip01(r4.x * s), g = clip01(g4v.x * s), bb = clip01(b4.x * s);
        acc  = 0.299f * r + 0.587f * g + 0.114f * bb;
        r = clip01(r4.y * s); g = clip01(g4v.y * s); bb = clip01(b4.y * s);
        acc += 0.299f * r + 0.587f * g + 0.114f * bb;
        r = clip01(r4.z * s); g = clip01(g4v.z * s); bb = clip01(b4.z * s);
        acc += 0.299f * r + 0.587f * g + 0.114f * bb;
        r = clip01(r4.w * s); g = clip01(g4v.w * s); bb = clip01(b4.w * s);
        acc += 0.299f * r + 0.587f * g + 0.114f * bb;
    }

    for (int off = 16; off > 0; off >>= 1)
        acc += __shfl_down_sync(0xFFFFFFFF, acc, off);

    __shared__ float warp_part[TPB / 32];
    const int lane = threadIdx.x & 31;
    const int wid  = threadIdx.x >> 5;
    if (lane == 0) warp_part[wid] = acc;
    __syncthreads();
    if (wid == 0) {
        float v = (lane < TPB / 32) ? warp_part[lane] : 0.0f;
        for (int off = 4; off > 0; off >>= 1)
            v += __shfl_down_sync(0xFFFFFFFF, v, off);
        if (lane == 0) d_part[b * PBLK + slot] = v;
    }
}

__device__ __forceinline__ float fracf(float x) { return x - floorf(x); }

// One channel of branchless HSV reconstruction: ch = minc + cr * clamp(|frac(u)*6-3|-1, 0, 1)
__device__ __forceinline__ float hsv_ch(float u, float cr, float minc) {
    float t = fracf(u);
    float a = fabsf(fmaf(t, 6.0f, -3.0f)) - 1.0f;
    float w = fminf(fmaxf(a, 0.0f), 1.0f);
    return fmaf(cr, w, minc);
}

// Pass 2: fused transform, images in REVERSE order (LIFO L2 reuse).
__global__ void __launch_bounds__(TPB) color_xform(const float* __restrict__ x,
                            const float* __restrict__ bfv,
                            const float* __restrict__ cfv,
                            const float* __restrict__ sfv,
                            const float* __restrict__ hfv,
                            float* __restrict__ out) {
    const int blk  = blockIdx.x;                 // 0 .. B*PBLK-1
    const int b    = (Bsz - 1) - blk / PBLK;     // reversed image order
    const int slot = blk % PBLK;
    const int g4   = slot * TPB + threadIdx.x;

    const float4* ibase = (const float4*)(x) + (size_t)b * 3 * HW4;
    float4*       obase = (float4*)(out)     + (size_t)b * 3 * HW4;

    // Long-latency pixel loads first (overlap with partial re-reduction).
    float4 rv = __ldcs(ibase + g4);
    float4 gv = __ldcs(ibase + g4 + HW4);
    float4 bv = __ldcs(ibase + g4 + 2 * HW4);

    // Re-reduce the 300 per-block partials for this image (L2-hot, deterministic).
    const int t = threadIdx.x;
    float acc = d_part[b * PBLK + t];
    if (t < PBLK - TPB) acc += d_part[b * PBLK + t + TPB];
    for (int off = 16; off > 0; off >>= 1)
        acc += __shfl_down_sync(0xFFFFFFFF, acc, off);
    __shared__ float warp_part[TPB / 32];
    __shared__ float s_mean;
    const int lane = t & 31;
    const int wid  = t >> 5;
    if (lane == 0) warp_part[wid] = acc;
    __syncthreads();
    if (wid == 0) {
        float v = (lane < TPB / 32) ? warp_part[lane] : 0.0f;
        for (int off = 4; off > 0; off >>= 1)
            v += __shfl_down_sync(0xFFFFFFFF, v, off);
        if (lane == 0) s_mean = v * (1.0f / (float)HW);
    }
    __syncthreads();
    const float mean = s_mean;

    const float bf = bfv[b];
    const float cf = cfv[b];
    const float sf = sfv[b];
    const float hf = hfv[b];
    // frac() is invariant to integer offsets, so fold both %1.0 mods and the
    // per-channel hue offsets into single frac calls: u_ch = hh/6 + hf + k_ch.
    const float hk_r = hf;                         // k=0  (== k=1 mod 1)
    const float hk_g = hf + (2.0f / 3.0f);
    const float hk_b = hf + (1.0f / 3.0f);

    float rr[4] = {rv.x, rv.y, rv.z, rv.w};
    float gg[4] = {gv.x, gv.y, gv.z, gv.w};
    float bb[4] = {bv.x, bv.y, bv.z, bv.w};

    #pragma unroll
    for (int k = 0; k < 4; k++) {
        float r  = clip01(rr[k] * bf);
        float g  = clip01(gg[k] * bf);
        float bl = clip01(bb[k] * bf);
        r  = clip01(cf * r  + (1.0f - cf) * mean);
        g  = clip01(cf * g  + (1.0f - cf) * mean);
        bl = clip01(cf * bl + (1.0f - cf) * mean);
        float gray = 0.299f * r + 0.587f * g + 0.114f * bl;
        r  = clip01(sf * r  + (1.0f - sf) * gray);
        g  = clip01(sf * g  + (1.0f - sf) * gray);
        bl = clip01(sf * bl + (1.0f - sf) * gray);

        // HSV hue rotation, restructured:
        //   v*s = cr,  v*(1-s) = minc  ->  ch = minc + cr * w_ch
        float maxc = fmaxf(r, fmaxf(g, bl));
        float minc = fminf(r, fminf(g, bl));
        float cr   = maxc - minc;
        float crd  = (cr == 0.0f) ? 1.0f : cr;
        float inv6 = __frcp_rn(crd) * (1.0f / 6.0f);

        bool pr = (maxc == r);
        bool pg = (maxc == g) && !pr;
        //  hh/6 = delta*inv6 + off6 ;  delta/off selected per sector
        float da   = pr ? g  : (pg ? bl : r);
        float db   = pr ? bl : (pg ? r  : g);
        float off6 = pr ? 0.0f : (pg ? (2.0f / 6.0f) : (4.0f / 6.0f));
        float hbase = fmaf(da - db, inv6, off6);

        rr[k] = hsv_ch(hbase + hk_r, cr, minc);
        gg[k] = hsv_ch(hbase + hk_g, cr, minc);
        bb[k] = hsv_ch(hbase + hk_b, cr, minc);
    }

    __stcs(obase + g4,           make_float4(rr[0], rr[1], rr[2], rr[3]));
    __stcs(obase + g4 + HW4,     make_float4(gg[0], gg[1], gg[2], gg[3]));
    __stcs(obase + g4 + 2 * HW4, make_float4(bb[0], bb[1], bb[2], bb[3]));
}

extern "C" void kernel_launch(void* const* d_in, const int* in_sizes, int n_in,
                              void* d_out, int out_size) {
    const float* x  = (const float*)d_in[0];
    const float* bf = (const float*)d_in[1];
    const float* cf = (const float*)d_in[2];
    const float* sf = (const float*)d_in[3];
    const float* hf = (const float*)d_in[4];
    float* out = (float*)d_out;

    gray_reduce<<<dim3(PBLK, Bsz), TPB>>>(x, bf);
    color_xform<<<Bsz * PBLK, TPB>>>(x, bf, cf, sf, hf, out);
}